// round 2
// baseline (speedup 1.0000x reference)
#include <cuda_runtime.h>

#define FR      256
#define DIN     512
#define HH      256
#define PNUM    6
#define MAXA    204800
#define MT_M    128
#define KC      16
#define NTHREADS 512
#define XSTR    132   // padded row stride (floats), keeps 16B alignment, breaks conflicts

// ---- scratch (static __device__ arrays: allocation-free per harness rules) ----
__device__ float g_theta[MAXA];
__device__ float g_mlp[PNUM][MAXA];

typedef unsigned long long ull;

__device__ __forceinline__ ull pack2(float x, float y) {
    ull r; asm("mov.b64 %0, {%1, %2};" : "=l"(r) : "f"(x), "f"(y)); return r;
}
__device__ __forceinline__ void unpack2(ull v, float &x, float &y) {
    asm("mov.b64 {%0, %1}, %2;" : "=f"(x), "=f"(y) : "l"(v));
}
// packed dual fp32 FMA (sm_103a f32x2 pipe: 2x the 3-reg FFMA rate)
__device__ __forceinline__ void fma2(ull &d, ull a, ull b) {
    asm("fma.rn.f32x2 %0, %1, %2, %0;" : "+l"(d) : "l"(a), "l"(b));
}

// ---------------------------------------------------------------------------
// Kernel 1: per-angle geometry -> theta
// NOTE: angles is int32 (JAX x64 disabled makes .astype(int64) a no-op to int32)
// ---------------------------------------------------------------------------
__global__ void geom_kernel(const float* __restrict__ xyz,
                            const int* __restrict__ angles, int A) {
    int i = blockIdx.x * blockDim.x + threadIdx.x;
    if (i >= A) return;
    int a0 = angles[3 * i + 0];
    int a1 = angles[3 * i + 1];
    int a2 = angles[3 * i + 2];
    float x0 = xyz[3 * a0 + 0], y0 = xyz[3 * a0 + 1], z0 = xyz[3 * a0 + 2];
    float x1 = xyz[3 * a1 + 0], y1 = xyz[3 * a1 + 1], z1 = xyz[3 * a1 + 2];
    float x2 = xyz[3 * a2 + 0], y2 = xyz[3 * a2 + 1], z2 = xyz[3 * a2 + 2];
    float v1x = x1 - x0, v1y = y1 - y0, v1z = z1 - z0;
    float v2x = x2 - x1, v2y = y2 - y1, v2z = z2 - z1;
    float dot = -(v1x * v2x + v1y * v2y + v1z * v2z);
    float nrm = sqrtf((v1x * v1x + v1y * v1y + v1z * v1z) *
                      (v2x * v2x + v2y * v2y + v2z * v2z));
    float ct = (dot / nrm) / 1.000001f;
    g_theta[i] = acosf(ct);
}

// ---------------------------------------------------------------------------
// Kernel 2: fused 3-layer MLP per (head p, tile of 128 angles)
//   layer1: X[128,512] @ W1[512,256] (X gathered from r inside K-loop)
//   layer2: tanh-out kept in smem, @ W2[256,256]
//   layer3: dot with W3[256] + warp reduce -> g_mlp[p][angle]
// ---------------------------------------------------------------------------
__device__ __forceinline__ float4 gather_x(const float* __restrict__ r,
                                           const int* sA, int grow, int kq, int k0) {
    int c = k0 + kq;
    if (c < FR) {
        float4 u = *(const float4*)(r + (size_t)sA[grow]       * FR + c);
        float4 w = *(const float4*)(r + (size_t)sA[256 + grow] * FR + c);
        return make_float4(u.x + w.x, u.y + w.y, u.z + w.z, u.w + w.w);
    } else {
        return *(const float4*)(r + (size_t)sA[128 + grow] * FR + (c - FR));
    }
}

__global__ void __launch_bounds__(NTHREADS, 1)
mlp_kernel(const float* __restrict__ r, const int* __restrict__ angles,
           const float* __restrict__ W1, const float* __restrict__ b1,
           const float* __restrict__ W2, const float* __restrict__ b2,
           const float* __restrict__ W3, const float* __restrict__ b3, int A) {
    extern __shared__ float smem[];
    float* sW = smem;                          // [2][KC][HH]
    float* sX = sW + 2 * KC * HH;              // [2][KC][XSTR]
    float* sH = sX + 2 * KC * XSTR;            // [HH][XSTR]  (layer-1 activations, k-major)
    int*   sA = (int*)(sH + HH * XSTR);        // [3][128]

    const int p    = blockIdx.y;
    const int m0   = blockIdx.x * MT_M;
    const int tid  = threadIdx.x;
    const int tx   = tid & 31;          // N microtile index (8 cols each)
    const int ty   = tid >> 5;          // M microtile index (8 rows each); warp == ty
    const int grow = tid >> 2;          // gather row 0..127
    const int kq   = (tid & 3) << 2;    // gather k sub-offset 0,4,8,12

    if (tid < MT_M) {
        int g = m0 + tid;
        int bidx = (g < A) ? 3 * g : 0;
        sA[tid]       = angles[bidx + 0];
        sA[128 + tid] = angles[bidx + 1];
        sA[256 + tid] = angles[bidx + 2];
    }
    __syncthreads();

    ull acc[8][4];
#pragma unroll
    for (int i = 0; i < 8; i++)
#pragma unroll
        for (int j = 0; j < 4; j++) acc[i][j] = 0ull;

    // ---------------- layer 1: K = 512 ----------------
    {
        const float4* wg = (const float4*)(W1 + (size_t)p * DIN * HH);
        {   // prologue: chunk 0
            float4 wa = wg[tid], wb = wg[tid + NTHREADS];
            float4 xv = gather_x(r, sA, grow, kq, 0);
            ((float4*)sW)[tid] = wa; ((float4*)sW)[tid + NTHREADS] = wb;
            sX[(kq + 0) * XSTR + grow] = xv.x; sX[(kq + 1) * XSTR + grow] = xv.y;
            sX[(kq + 2) * XSTR + grow] = xv.z; sX[(kq + 3) * XSTR + grow] = xv.w;
        }
        __syncthreads();
        const int NC = DIN / KC;  // 32
        for (int c = 0; c < NC; c++) {
            float4 wa, wb, xv;
            if (c + 1 < NC) {
                const float4* wn = wg + (size_t)(c + 1) * KC * HH / 4;
                wa = wn[tid]; wb = wn[tid + NTHREADS];
                xv = gather_x(r, sA, grow, kq, (c + 1) * KC);
            }
            const float* sWb = sW + (c & 1) * KC * HH;
            const float* sXb = sX + (c & 1) * KC * XSTR;
#pragma unroll
            for (int k = 0; k < KC; k++) {
                const float* xr = sXb + k * XSTR + ty * 8;
                float4 xa = *(const float4*)xr;
                float4 xb = *(const float4*)(xr + 4);
                const ulonglong2* wr = (const ulonglong2*)(sWb + k * HH + tx * 8);
                ulonglong2 wlo = wr[0], whi = wr[1];
                float xs[8] = {xa.x, xa.y, xa.z, xa.w, xb.x, xb.y, xb.z, xb.w};
#pragma unroll
                for (int i = 0; i < 8; i++) {
                    ull xx = pack2(xs[i], xs[i]);
                    fma2(acc[i][0], xx, wlo.x);
                    fma2(acc[i][1], xx, wlo.y);
                    fma2(acc[i][2], xx, whi.x);
                    fma2(acc[i][3], xx, whi.y);
                }
            }
            if (c + 1 < NC) {
                __syncthreads();
                float* wd = sW + ((c + 1) & 1) * KC * HH;
                ((float4*)wd)[tid] = wa; ((float4*)wd)[tid + NTHREADS] = wb;
                float* xd = sX + ((c + 1) & 1) * KC * XSTR;
                xd[(kq + 0) * XSTR + grow] = xv.x; xd[(kq + 1) * XSTR + grow] = xv.y;
                xd[(kq + 2) * XSTR + grow] = xv.z; xd[(kq + 3) * XSTR + grow] = xv.w;
                __syncthreads();
            }
        }
    }

    // epilogue 1: bias + tanh -> sH (k-major), reset acc
    {
        const float* b1p = b1 + p * HH + tx * 8;
        float bb[8];
#pragma unroll
        for (int j = 0; j < 8; j++) bb[j] = b1p[j];
#pragma unroll
        for (int i = 0; i < 8; i++) {
            int m = ty * 8 + i;
#pragma unroll
            for (int j = 0; j < 4; j++) {
                float lo, hi; unpack2(acc[i][j], lo, hi);
                sH[(tx * 8 + 2 * j + 0) * XSTR + m] = tanhf(lo + bb[2 * j + 0]);
                sH[(tx * 8 + 2 * j + 1) * XSTR + m] = tanhf(hi + bb[2 * j + 1]);
                acc[i][j] = 0ull;
            }
        }
    }
    __syncthreads();

    // ---------------- layer 2: K = 256 (X side read directly from sH) ----------------
    {
        const float4* wg = (const float4*)(W2 + (size_t)p * HH * HH);
        {
            float4 wa = wg[tid], wb = wg[tid + NTHREADS];
            ((float4*)sW)[tid] = wa; ((float4*)sW)[tid + NTHREADS] = wb;
        }
        __syncthreads();
        const int NC = HH / KC;  // 16
        for (int c = 0; c < NC; c++) {
            float4 wa, wb;
            if (c + 1 < NC) {
                const float4* wn = wg + (size_t)(c + 1) * KC * HH / 4;
                wa = wn[tid]; wb = wn[tid + NTHREADS];
            }
            const float* sWb = sW + (c & 1) * KC * HH;
            const float* sXb = sH + c * KC * XSTR;
#pragma unroll
            for (int k = 0; k < KC; k++) {
                const float* xr = sXb + k * XSTR + ty * 8;
                float4 xa = *(const float4*)xr;
                float4 xb = *(const float4*)(xr + 4);
                const ulonglong2* wr = (const ulonglong2*)(sWb + k * HH + tx * 8);
                ulonglong2 wlo = wr[0], whi = wr[1];
                float xs[8] = {xa.x, xa.y, xa.z, xa.w, xb.x, xb.y, xb.z, xb.w};
#pragma unroll
                for (int i = 0; i < 8; i++) {
                    ull xx = pack2(xs[i], xs[i]);
                    fma2(acc[i][0], xx, wlo.x);
                    fma2(acc[i][1], xx, wlo.y);
                    fma2(acc[i][2], xx, whi.x);
                    fma2(acc[i][3], xx, whi.y);
                }
            }
            if (c + 1 < NC) {
                __syncthreads();
                float* wd = sW + ((c + 1) & 1) * KC * HH;
                ((float4*)wd)[tid] = wa; ((float4*)wd)[tid + NTHREADS] = wb;
                __syncthreads();
            }
        }
    }

    // epilogue 2 + layer 3: tanh, dot with W3 column, warp reduce over tx
    {
        const float* b2p = b2 + p * HH + tx * 8;
        const float* w3p = W3 + p * HH + tx * 8;
        float part[8];
#pragma unroll
        for (int i = 0; i < 8; i++) {
            float s = 0.0f;
#pragma unroll
            for (int j = 0; j < 4; j++) {
                float lo, hi; unpack2(acc[i][j], lo, hi);
                s += tanhf(lo + b2p[2 * j + 0]) * w3p[2 * j + 0];
                s += tanhf(hi + b2p[2 * j + 1]) * w3p[2 * j + 1];
            }
            part[i] = s;
        }
#pragma unroll
        for (int off = 16; off > 0; off >>= 1)
#pragma unroll
            for (int i = 0; i < 8; i++)
                part[i] += __shfl_down_sync(0xffffffffu, part[i], off);
        if (tx == 0) {
            float bb3 = b3[p];
#pragma unroll
            for (int i = 0; i < 8; i++) {
                int g = m0 + ty * 8 + i;
                if (g < A) g_mlp[p][g] = part[i] + bb3;
            }
        }
    }
}

// ---------------------------------------------------------------------------
// Kernel 3: E(theta, outs) + deterministic per-segment reduction
// ---------------------------------------------------------------------------
__global__ void seg_kernel(const int* __restrict__ num_angles, float* __restrict__ out, int A) {
    const float TH0 = 1.3824383f;   // sqrt(109.5*pi/180)
    const float KH  = 3.1622777f;   // sqrt(10)
    int b = blockIdx.x;
    int start = 0;
    for (int i = 0; i < b; i++) start += num_angles[i];
    int cnt = num_angles[b];
    if (start + cnt > A) cnt = A - start;

    float accv = 0.0f;
    for (int i = threadIdx.x; i < cnt; i += blockDim.x) {
        int g = start + i;
        float th = g_theta[g];
        float o0 = g_mlp[0][g], o1 = g_mlp[1][g], o2 = g_mlp[2][g];
        float o3 = g_mlp[3][g], o4 = g_mlp[4][g], o5 = g_mlp[5][g];
        float t0h = TH0 + o0; t0h *= t0h;
        float kh  = KH + o1;  kh  *= kh;
        float d   = th - t0h;
        float E   = 0.5f * kh * d * d;
        float t0c = o2 * o2, kc = o3 * o3;
        float dc  = th - t0c;
        E += 0.5f * kc * dc * dc * dc;
        float t0q = o4 * o4, kqv = o5 * o5;
        float dq  = th - t0q; float dq2 = dq * dq;
        E += 0.5f * kqv * dq2 * dq2;
        accv += E;
    }
    __shared__ float red[256];
    red[threadIdx.x] = accv;
    __syncthreads();
    for (int s = 128; s > 0; s >>= 1) {
        if (threadIdx.x < s) red[threadIdx.x] += red[threadIdx.x + s];
        __syncthreads();
    }
    if (threadIdx.x == 0) out[b] = red[0];
}

// ---------------------------------------------------------------------------
extern "C" void kernel_launch(void* const* d_in, const int* in_sizes, int n_in,
                              void* d_out, int out_size) {
    const float* r          = (const float*)d_in[0];
    const float* xyz        = (const float*)d_in[1];
    const int*   angles     = (const int*)d_in[2];
    const int*   num_angles = (const int*)d_in[3];
    const float* W1 = (const float*)d_in[4];
    const float* b1 = (const float*)d_in[5];
    const float* W2 = (const float*)d_in[6];
    const float* b2 = (const float*)d_in[7];
    const float* W3 = (const float*)d_in[8];
    const float* b3 = (const float*)d_in[9];
    int A = in_sizes[2] / 3;
    int B = in_sizes[3];

    size_t smem = (size_t)(2 * KC * HH + 2 * KC * XSTR + HH * XSTR) * sizeof(float)
                + 3 * MT_M * sizeof(int);
    cudaFuncSetAttribute(mlp_kernel, cudaFuncAttributeMaxDynamicSharedMemorySize, (int)smem);

    geom_kernel<<<(A + 255) / 256, 256>>>(xyz, angles, A);
    dim3 grid((A + MT_M - 1) / MT_M, PNUM);
    mlp_kernel<<<grid, NTHREADS, smem>>>(r, angles, W1, b1, W2, b2, W3, b3, A);
    seg_kernel<<<B, 256>>>(num_angles, (float*)d_out, A);
}

// round 7
// speedup vs baseline: 2.0413x; 2.0413x over previous
#include <cuda_runtime.h>

#define FR   256
#define DIN  512
#define HH   256
#define PNUM 6
#define MAXA 204800

// ---------------- static device scratch ----------------
__device__ float g_theta[MAXA];
__device__ float g_mlp[PNUM][MAXA];
__device__ unsigned int g_W1T[PNUM * HH * DIN];  // [p][n][k] tf32 bits (W1 transposed)
__device__ unsigned int g_W2T[PNUM * HH * HH];   // [p][n][k] tf32 bits

__device__ __forceinline__ unsigned f2tf(float x) {
    unsigned u; asm("cvt.rna.tf32.f32 %0, %1;" : "=r"(u) : "f"(x)); return u;
}
// NaN-safe fast tanh: 1 - 2/(e^{2x}+1). x=+inf -> 1, x=-inf -> -1.
__device__ __forceinline__ float fast_tanh(float x) {
    float e = __expf(2.0f * x);
    return 1.0f - __fdividef(2.0f, e + 1.0f);
}
__device__ __forceinline__ void mma_tf32(float* c, const unsigned* a, const unsigned* b) {
    asm volatile(
        "mma.sync.aligned.m16n8k8.row.col.f32.tf32.tf32.f32 "
        "{%0,%1,%2,%3}, {%4,%5,%6,%7}, {%8,%9}, {%0,%1,%2,%3};"
        : "+f"(c[0]), "+f"(c[1]), "+f"(c[2]), "+f"(c[3])
        : "r"(a[0]), "r"(a[1]), "r"(a[2]), "r"(a[3]), "r"(b[0]), "r"(b[1]));
}

// ---------------- smem layout (floats) ----------------
#define XBUF  2560            // 128 rows * 20
#define WBUF  5120            // 256 rows * 20
#define HSTR  260
#define OFF_SX   0
#define OFF_SW   (OFF_SX + 2 * XBUF)
#define OFF_SH   (OFF_SW + 2 * WBUF)
#define OFF_B1S  (OFF_SH + 128 * HSTR)
#define OFF_B2S  (OFF_B1S + 256)
#define OFF_W3S  (OFF_B2S + 256)
#define OFF_RED  (OFF_W3S + 256)
#define OFF_IDX  (OFF_RED + 512)
#define SMEM_FLOATS (OFF_IDX + 384)
#define SMEM_TOT (SMEM_FLOATS * 4)

// ---------------------------------------------------------------------------
// prep: transpose + tf32-convert weights: W[p][k][n] -> WT[p][n][k]
// ---------------------------------------------------------------------------
__global__ void prep_w1(const float* __restrict__ W1) {
    __shared__ float tile[32][33];
    int p = blockIdx.z, i0 = blockIdx.x * 32, j0 = blockIdx.y * 32;
    int tx = threadIdx.x, ty = threadIdx.y;
    for (int d = ty; d < 32; d += 8)
        tile[d][tx] = W1[((size_t)p * DIN + i0 + d) * HH + j0 + tx];
    __syncthreads();
    for (int d = ty; d < 32; d += 8)
        g_W1T[((size_t)p * HH + j0 + d) * DIN + i0 + tx] = f2tf(tile[tx][d]);
}
__global__ void prep_w2(const float* __restrict__ W2) {
    __shared__ float tile[32][33];
    int p = blockIdx.z, i0 = blockIdx.x * 32, j0 = blockIdx.y * 32;
    int tx = threadIdx.x, ty = threadIdx.y;
    for (int d = ty; d < 32; d += 8)
        tile[d][tx] = W2[((size_t)p * HH + i0 + d) * HH + j0 + tx];
    __syncthreads();
    for (int d = ty; d < 32; d += 8)
        g_W2T[((size_t)p * HH + j0 + d) * HH + i0 + tx] = f2tf(tile[tx][d]);
}

// ---------------------------------------------------------------------------
// geometry -> theta
// ---------------------------------------------------------------------------
__global__ void geom_kernel(const float* __restrict__ xyz,
                            const int* __restrict__ angles, int A) {
    int i = blockIdx.x * blockDim.x + threadIdx.x;
    if (i >= A) return;
    int a0 = angles[3 * i], a1 = angles[3 * i + 1], a2 = angles[3 * i + 2];
    float x0 = xyz[3 * a0], y0 = xyz[3 * a0 + 1], z0 = xyz[3 * a0 + 2];
    float x1 = xyz[3 * a1], y1 = xyz[3 * a1 + 1], z1 = xyz[3 * a1 + 2];
    float x2 = xyz[3 * a2], y2 = xyz[3 * a2 + 1], z2 = xyz[3 * a2 + 2];
    float v1x = x1 - x0, v1y = y1 - y0, v1z = z1 - z0;
    float v2x = x2 - x1, v2y = y2 - y1, v2z = z2 - z1;
    float dot = -(v1x * v2x + v1y * v2y + v1z * v2z);
    float nrm = sqrtf((v1x * v1x + v1y * v1y + v1z * v1z) *
                      (v2x * v2x + v2y * v2y + v2z * v2z));
    g_theta[i] = acosf((dot / nrm) / 1.000001f);
}

// ---------------------------------------------------------------------------
// fused MLP via mma.sync tf32. CTA = (128 angles, head p). 8 warps = 2x4.
// ---------------------------------------------------------------------------
__global__ void __launch_bounds__(256, 1)
mlp_mma_kernel(const float* __restrict__ r, const int* __restrict__ angles,
               const float* __restrict__ b1, const float* __restrict__ b2,
               const float* __restrict__ W3, const float* __restrict__ b3, int A) {
    extern __shared__ float smem[];
    float* sX  = smem + OFF_SX;
    float* sW  = smem + OFF_SW;
    float* sH  = smem + OFF_SH;
    float* b1s = smem + OFF_B1S;
    float* b2s = smem + OFF_B2S;
    float* w3s = smem + OFF_W3S;
    float* sRed = smem + OFF_RED;
    int*   sIdx = (int*)(smem + OFF_IDX);

    const int tid = threadIdx.x, lane = tid & 31;
    const int w = tid >> 5, wr = w & 1, wc = w >> 1;   // warp grid 2 (rows) x 4 (cols)
    const int g = lane >> 2, t4 = lane & 3;
    const int p = blockIdx.y, m0 = blockIdx.x * 128;

    if (tid < 128) {
        int gg = m0 + tid;
        int bi = (gg < A) ? 3 * gg : 0;
        sIdx[tid] = angles[bi]; sIdx[128 + tid] = angles[bi + 1]; sIdx[256 + tid] = angles[bi + 2];
    }
    b1s[tid] = b1[p * HH + tid];
    b2s[tid] = b2[p * HH + tid];
    w3s[tid] = W3[p * HH + tid];
    __syncthreads();   // sIdx must be visible to ALL threads before the first gather

    const unsigned* w1src = g_W1T + (size_t)p * HH * DIN;
    const unsigned* w2src = g_W2T + (size_t)p * HH * HH;

    // chunk loaders (KC = 16)
    auto loadX1 = [&](int c, int b) {
        unsigned* dst = (unsigned*)(sX + b * XBUF);
#pragma unroll
        for (int q = 0; q < 2; q++) {
            int idx = tid + 256 * q;
            int row = idx >> 2, kl = (idx & 3) * 4, kg = c * 16 + kl;
            float4 v;
            if (kg < FR) {
                float4 u = *(const float4*)(r + (size_t)sIdx[row] * FR + kg);
                float4 x = *(const float4*)(r + (size_t)sIdx[256 + row] * FR + kg);
                v = make_float4(u.x + x.x, u.y + x.y, u.z + x.z, u.w + x.w);
            } else {
                v = *(const float4*)(r + (size_t)sIdx[128 + row] * FR + kg - FR);
            }
            uint4 t = make_uint4(f2tf(v.x), f2tf(v.y), f2tf(v.z), f2tf(v.w));
            *(uint4*)(dst + row * 20 + kl) = t;
        }
    };
    auto loadW = [&](const unsigned* src, int stride, int c, int b) {
        unsigned* dst = (unsigned*)(sW + b * WBUF);
#pragma unroll
        for (int q = 0; q < 4; q++) {
            int idx = tid + 256 * q;
            int j = idx >> 2, kl = (idx & 3) * 4;
            uint4 v = *(const uint4*)(src + (size_t)j * stride + c * 16 + kl);
            *(uint4*)(dst + j * 20 + kl) = v;
        }
    };

    float acc[4][8][4];
#pragma unroll
    for (int i = 0; i < 4; i++)
#pragma unroll
        for (int j = 0; j < 8; j++)
#pragma unroll
            for (int q = 0; q < 4; q++) acc[i][j][q] = 0.0f;

    // one 16-deep K chunk of MMAs; Xb has row stride xstr, k window at k0
    auto compute = [&](const unsigned* Xb, int xstr, int k0, const unsigned* Wb) {
#pragma unroll
        for (int kk = 0; kk < 16; kk += 8) {
            unsigned a[4][4], bfr[8][2];
#pragma unroll
            for (int i = 0; i < 4; i++) {
                int rb = (wr * 64 + i * 16 + g) * xstr + k0 + kk + t4;
                a[i][0] = Xb[rb];
                a[i][1] = Xb[rb + 8 * xstr];
                a[i][2] = Xb[rb + 4];
                a[i][3] = Xb[rb + 8 * xstr + 4];
            }
#pragma unroll
            for (int j = 0; j < 8; j++) {
                int nb = (wc * 64 + j * 8 + g) * 20 + kk + t4;
                bfr[j][0] = Wb[nb];
                bfr[j][1] = Wb[nb + 4];
            }
#pragma unroll
            for (int i = 0; i < 4; i++)
#pragma unroll
                for (int j = 0; j < 8; j++) mma_tf32(acc[i][j], a[i], bfr[j]);
        }
    };

    // ================= layer 1: K = 512, 32 chunks =================
    loadX1(0, 0); loadW(w1src, DIN, 0, 0);
    __syncthreads();
    for (int c = 0; c < 32; c++) {
        if (c + 1 < 32) { loadX1(c + 1, (c + 1) & 1); loadW(w1src, DIN, c + 1, (c + 1) & 1); }
        compute((const unsigned*)(sX + (c & 1) * XBUF), 20, 0,
                (const unsigned*)(sW + (c & 1) * WBUF));
        __syncthreads();
    }

    // epilogue 1: bias + tanh -> sH (tf32 bits, stride HSTR), reset acc
    {
        unsigned* sHu = (unsigned*)sH;
#pragma unroll
        for (int i = 0; i < 4; i++) {
            int row0 = wr * 64 + i * 16 + g;
#pragma unroll
            for (int j = 0; j < 8; j++) {
                int col = wc * 64 + j * 8 + t4 * 2;
                sHu[row0 * HSTR + col]       = f2tf(fast_tanh(acc[i][j][0] + b1s[col]));
                sHu[row0 * HSTR + col + 1]   = f2tf(fast_tanh(acc[i][j][1] + b1s[col + 1]));
                sHu[(row0 + 8) * HSTR + col]     = f2tf(fast_tanh(acc[i][j][2] + b1s[col]));
                sHu[(row0 + 8) * HSTR + col + 1] = f2tf(fast_tanh(acc[i][j][3] + b1s[col + 1]));
                acc[i][j][0] = acc[i][j][1] = acc[i][j][2] = acc[i][j][3] = 0.0f;
            }
        }
    }
    __syncthreads();

    // ================= layer 2: K = 256, 16 chunks (A = sH) =================
    loadW(w2src, HH, 0, 0);
    __syncthreads();
    for (int c = 0; c < 16; c++) {
        if (c + 1 < 16) loadW(w2src, HH, c + 1, (c + 1) & 1);
        compute((const unsigned*)sH, HSTR, c * 16,
                (const unsigned*)(sW + (c & 1) * WBUF));
        __syncthreads();
    }

    // epilogue 2: tanh + dot W3 + reduce -> g_mlp
    {
#pragma unroll
        for (int i = 0; i < 4; i++) {
            float v0 = 0.0f, v1 = 0.0f;
#pragma unroll
            for (int j = 0; j < 8; j++) {
                int col = wc * 64 + j * 8 + t4 * 2;
                v0 += fast_tanh(acc[i][j][0] + b2s[col]) * w3s[col]
                    + fast_tanh(acc[i][j][1] + b2s[col + 1]) * w3s[col + 1];
                v1 += fast_tanh(acc[i][j][2] + b2s[col]) * w3s[col]
                    + fast_tanh(acc[i][j][3] + b2s[col + 1]) * w3s[col + 1];
            }
            v0 += __shfl_xor_sync(0xffffffffu, v0, 1);
            v0 += __shfl_xor_sync(0xffffffffu, v0, 2);
            v1 += __shfl_xor_sync(0xffffffffu, v1, 1);
            v1 += __shfl_xor_sync(0xffffffffu, v1, 2);
            if (t4 == 0) {
                int row0 = wr * 64 + i * 16 + g;
                sRed[wc * 128 + row0]     = v0;
                sRed[wc * 128 + row0 + 8] = v1;
            }
        }
    }
    __syncthreads();
    if (tid < 128) {
        int gg = m0 + tid;
        if (gg < A)
            g_mlp[p][gg] = sRed[tid] + sRed[128 + tid] + sRed[256 + tid] + sRed[384 + tid] + b3[p];
    }
}

// ---------------------------------------------------------------------------
// E(theta, outs) + deterministic per-segment reduction
// ---------------------------------------------------------------------------
__global__ void seg_kernel(const int* __restrict__ num_angles, float* __restrict__ out, int A) {
    const float TH0 = 1.3824383f, KH = 3.1622777f;
    int b = blockIdx.x;
    int start = 0;
    for (int i = 0; i < b; i++) start += num_angles[i];
    int cnt = num_angles[b];
    if (start + cnt > A) cnt = A - start;

    float accv = 0.0f;
    for (int i = threadIdx.x; i < cnt; i += blockDim.x) {
        int g = start + i;
        float th = g_theta[g];
        float o0 = g_mlp[0][g], o1 = g_mlp[1][g], o2 = g_mlp[2][g];
        float o3 = g_mlp[3][g], o4 = g_mlp[4][g], o5 = g_mlp[5][g];
        float t0h = TH0 + o0; t0h *= t0h;
        float kh = KH + o1; kh *= kh;
        float d = th - t0h;
        float E = 0.5f * kh * d * d;
        float t0c = o2 * o2, kc = o3 * o3;
        float dc = th - t0c;
        E += 0.5f * kc * dc * dc * dc;
        float t0q = o4 * o4, kq = o5 * o5;
        float dq = th - t0q, dq2 = dq * dq;
        E += 0.5f * kq * dq2 * dq2;
        accv += E;
    }
    __shared__ float red[256];
    red[threadIdx.x] = accv;
    __syncthreads();
    for (int s = 128; s > 0; s >>= 1) {
        if (threadIdx.x < s) red[threadIdx.x] += red[threadIdx.x + s];
        __syncthreads();
    }
    if (threadIdx.x == 0) out[b] = red[0];
}

// ---------------------------------------------------------------------------
extern "C" void kernel_launch(void* const* d_in, const int* in_sizes, int n_in,
                              void* d_out, int out_size) {
    const float* r          = (const float*)d_in[0];
    const float* xyz        = (const float*)d_in[1];
    const int*   angles     = (const int*)d_in[2];
    const int*   num_angles = (const int*)d_in[3];
    const float* W1 = (const float*)d_in[4];
    const float* b1 = (const float*)d_in[5];
    const float* W2 = (const float*)d_in[6];
    const float* b2 = (const float*)d_in[7];
    const float* W3 = (const float*)d_in[8];
    const float* b3 = (const float*)d_in[9];
    int A = in_sizes[2] / 3;
    int B = in_sizes[3];

    cudaFuncSetAttribute(mlp_mma_kernel, cudaFuncAttributeMaxDynamicSharedMemorySize, SMEM_TOT);

    prep_w1<<<dim3(DIN / 32, HH / 32, PNUM), dim3(32, 8)>>>(W1);
    prep_w2<<<dim3(HH / 32, HH / 32, PNUM), dim3(32, 8)>>>(W2);
    geom_kernel<<<(A + 255) / 256, 256>>>(xyz, angles, A);
    dim3 grid((A + 127) / 128, PNUM);
    mlp_mma_kernel<<<grid, 256, SMEM_TOT>>>(r, angles, b1, b2, W3, b3, A);
    seg_kernel<<<B, 256>>>(num_angles, (float*)d_out, A);
}

// round 9
// speedup vs baseline: 2.6066x; 1.2770x over previous
#include <cuda_runtime.h>

#define FR   256
#define DIN  512
#define HH   256
#define PNUM 6
#define MAXA 204800

// ---------------- static device scratch ----------------
__device__ float g_theta[MAXA];
__device__ float g_mlp[PNUM][MAXA];
// fragment-packed tf32 weights: per head, per 16-k chunk, 1024 x 16B units
__device__ unsigned int g_W1P[PNUM * 32 * 4096];  // 6*32 chunks * 4096 floats
__device__ unsigned int g_W2P[PNUM * 16 * 4096];  // 6*16 chunks * 4096 floats

__device__ __forceinline__ unsigned f2tf(float x) {
    unsigned u; asm("cvt.rna.tf32.f32 %0, %1;" : "=r"(u) : "f"(x)); return u;
}
// NaN-safe fast tanh: 1 - 2/(e^{2x}+1)
__device__ __forceinline__ float fast_tanh(float x) {
    float e = __expf(2.0f * x);
    return 1.0f - __fdividef(2.0f, e + 1.0f);
}
__device__ __forceinline__ void mma_tf32(float* c, const unsigned* a, const unsigned* b) {
    asm volatile(
        "mma.sync.aligned.m16n8k8.row.col.f32.tf32.tf32.f32 "
        "{%0,%1,%2,%3}, {%4,%5,%6,%7}, {%8,%9}, {%0,%1,%2,%3};"
        : "+f"(c[0]), "+f"(c[1]), "+f"(c[2]), "+f"(c[3])
        : "r"(a[0]), "r"(a[1]), "r"(a[2]), "r"(a[3]), "r"(b[0]), "r"(b[1]));
}
__device__ __forceinline__ unsigned smem_u32(const void* p) {
    unsigned a;
    asm("{ .reg .u64 t; cvta.to.shared.u64 t, %1; cvt.u32.u64 %0, t; }" : "=r"(a) : "l"(p));
    return a;
}
#define CP_ASYNC16(dst, src) asm volatile("cp.async.cg.shared.global [%0], [%1], 16;" :: "r"(dst), "l"(src) : "memory")
#define CP_COMMIT() asm volatile("cp.async.commit_group;" ::: "memory")
#define CP_WAIT0()  asm volatile("cp.async.wait_group 0;" ::: "memory")

// ---------------- smem layout (floats) ----------------
#define XBUF  2048            // one packed 128x16 A chunk
#define WBUF  4096            // one packed 256x16 B chunk
#define OFF_SX   0
#define OFF_SW   (OFF_SX + 2 * XBUF)
#define OFF_SH   (OFF_SW + 2 * WBUF)              // 16 packed A chunks = 32768
#define OFF_B1S  (OFF_SH + 32768)
#define OFF_B2S  (OFF_B1S + 256)
#define OFF_W3S  (OFF_B2S + 256)
#define OFF_RED  (OFF_W3S + 256)
#define OFF_IDX  (OFF_RED + 512)
#define SMEM_FLOATS (OFF_IDX + 384)
#define SMEM_TOT (SMEM_FLOATS * 4)

// ---------------------------------------------------------------------------
// prep: W[p][k][n] -> fragment-packed tf32 units.
// unit ub = (wc*8+j)*32 + g*4 + t4 ; n = wc*64+j*8+g ; floats d=0..3: k = c*16 + t4 + 4d
// ---------------------------------------------------------------------------
__global__ void prep_w1(const float* __restrict__ W1) {
    int u = blockIdx.x * 256 + threadIdx.x;   // 196608 units
    int p = u >> 15, rem = u & 32767;
    int c = rem >> 10, ub = rem & 1023;
    int lane = ub & 31, g = lane >> 2, t4 = lane & 3;
    int j = (ub >> 5) & 7, wcq = ub >> 8;
    int n = wcq * 64 + j * 8 + g;
    const float* src = W1 + ((size_t)p * DIN + c * 16 + t4) * HH + n;
    uint4 o;
    o.x = f2tf(src[0]); o.y = f2tf(src[4 * HH]);
    o.z = f2tf(src[8 * HH]); o.w = f2tf(src[12 * HH]);
    *(uint4*)(g_W1P + (size_t)u * 4) = o;
}
__global__ void prep_w2(const float* __restrict__ W2) {
    int u = blockIdx.x * 256 + threadIdx.x;   // 98304 units
    int p = u >> 14, rem = u & 16383;
    int c = rem >> 10, ub = rem & 1023;
    int lane = ub & 31, g = lane >> 2, t4 = lane & 3;
    int j = (ub >> 5) & 7, wcq = ub >> 8;
    int n = wcq * 64 + j * 8 + g;
    const float* src = W2 + ((size_t)p * HH + c * 16 + t4) * HH + n;
    uint4 o;
    o.x = f2tf(src[0]); o.y = f2tf(src[4 * HH]);
    o.z = f2tf(src[8 * HH]); o.w = f2tf(src[12 * HH]);
    *(uint4*)(g_W2P + (size_t)u * 4) = o;
}

// ---------------------------------------------------------------------------
// geometry -> theta
// ---------------------------------------------------------------------------
__global__ void geom_kernel(const float* __restrict__ xyz,
                            const int* __restrict__ angles, int A) {
    int i = blockIdx.x * blockDim.x + threadIdx.x;
    if (i >= A) return;
    int a0 = angles[3 * i], a1 = angles[3 * i + 1], a2 = angles[3 * i + 2];
    float x0 = xyz[3 * a0], y0 = xyz[3 * a0 + 1], z0 = xyz[3 * a0 + 2];
    float x1 = xyz[3 * a1], y1 = xyz[3 * a1 + 1], z1 = xyz[3 * a1 + 2];
    float x2 = xyz[3 * a2], y2 = xyz[3 * a2 + 1], z2 = xyz[3 * a2 + 2];
    float v1x = x1 - x0, v1y = y1 - y0, v1z = z1 - z0;
    float v2x = x2 - x1, v2y = y2 - y1, v2z = z2 - z1;
    float dot = -(v1x * v2x + v1y * v2y + v1z * v2z);
    float nrm = sqrtf((v1x * v1x + v1y * v1y + v1z * v1z) *
                      (v2x * v2x + v2y * v2y + v2z * v2z));
    g_theta[i] = acosf((dot / nrm) / 1.000001f);
}

// ---------------------------------------------------------------------------
// fused MLP, mma.sync tf32 with packed LDS.128 fragments. 8 warps = 2x4.
// ---------------------------------------------------------------------------
__global__ void __launch_bounds__(256, 1)
mlp_mma_kernel(const float* __restrict__ r, const int* __restrict__ angles,
               const float* __restrict__ b1, const float* __restrict__ b2,
               const float* __restrict__ W3, const float* __restrict__ b3, int A) {
    extern __shared__ float smem[];
    float* sX  = smem + OFF_SX;
    float* sW  = smem + OFF_SW;
    float* sH  = smem + OFF_SH;
    float* b1s = smem + OFF_B1S;
    float* b2s = smem + OFF_B2S;
    float* w3s = smem + OFF_W3S;
    float* sRed = smem + OFF_RED;
    int*   sIdx = (int*)(smem + OFF_IDX);

    const int tid = threadIdx.x, lane = tid & 31;
    const int w = tid >> 5, wr = w & 1, wc = w >> 1;
    const int g = lane >> 2, t4 = lane & 3;
    const int p = blockIdx.y, m0 = blockIdx.x * 128;
    const unsigned swBase = smem_u32(sW);

    if (tid < 128) {
        int gg = m0 + tid;
        int bi = (gg < A) ? 3 * gg : 0;
        sIdx[tid] = angles[bi]; sIdx[128 + tid] = angles[bi + 1]; sIdx[256 + tid] = angles[bi + 2];
    }
    b1s[tid] = b1[p * HH + tid];
    b2s[tid] = b2[p * HH + tid];
    w3s[tid] = W3[p * HH + tid];
    __syncthreads();

    const unsigned* w1p = g_W1P + (size_t)p * 32 * 4096;
    const unsigned* w2p = g_W2P + (size_t)p * 16 * 4096;

    // gather X chunk -> packed A layout (swizzled scatter)
    auto loadX1 = [&](int c, int b) {
        unsigned* dst = (unsigned*)(sX + b * XBUF);
#pragma unroll
        for (int q = 0; q < 2; q++) {
            int idx = tid + 256 * q;
            int row = idx >> 2, kl = (idx & 3) * 4, kg = c * 16 + kl;
            float4 v;
            if (kg < FR) {
                float4 u = *(const float4*)(r + (size_t)sIdx[row] * FR + kg);
                float4 x = *(const float4*)(r + (size_t)sIdx[256 + row] * FR + kg);
                v = make_float4(u.x + x.x, u.y + x.y, u.z + x.z, u.w + x.w);
            } else {
                v = *(const float4*)(r + (size_t)sIdx[128 + row] * FR + kg - FR);
            }
            unsigned f[4] = {f2tf(v.x), f2tf(v.y), f2tf(v.z), f2tf(v.w)};
            int t = row >> 4, gr = row & 7, half = (row >> 3) & 1;
            int kk = kl >> 3, q2 = (kl >> 2) & 1;
#pragma unroll
            for (int e = 0; e < 4; e++) {
                unsigned u16 = t * 64 + (gr * 4 + e) * 2 + kk;
                unsigned us = u16 ^ ((u16 >> 3) & 7);
                dst[us * 4 + q2 * 2 + half] = f[e];
            }
        }
    };
    // linear cp.async copy of one packed W chunk (16 KB)
    auto loadW = [&](const unsigned* srcChunk, int b) {
        unsigned dst = swBase + (unsigned)(b * WBUF * 4);
#pragma unroll
        for (int q = 0; q < 4; q++) {
            int idx = tid + 256 * q;
            CP_ASYNC16(dst + idx * 16, srcChunk + (size_t)idx * 4);
        }
    };

    float acc[4][8][4];
#pragma unroll
    for (int i = 0; i < 4; i++)
#pragma unroll
        for (int j = 0; j < 8; j++)
#pragma unroll
            for (int q = 0; q < 4; q++) acc[i][j][q] = 0.0f;

    // one 16-k chunk: 8 B LDS.128 + 8 A LDS.128 + 64 MMA per warp
    auto compute = [&](const unsigned* Xb, const unsigned* Wb) {
        uint4 B[8];
#pragma unroll
        for (int j = 0; j < 8; j++)
            B[j] = *(const uint4*)(Wb + ((wc * 8 + j) * 32 + lane) * 4);
#pragma unroll
        for (int i = 0; i < 4; i++) {
            int t = wr * 4 + i;
#pragma unroll
            for (int kk = 0; kk < 2; kk++) {
                unsigned u16 = t * 64 + lane * 2 + kk;
                unsigned us = u16 ^ ((u16 >> 3) & 7);
                uint4 Aa = *(const uint4*)(Xb + us * 4);
                unsigned a[4] = {Aa.x, Aa.y, Aa.z, Aa.w};
#pragma unroll
                for (int j = 0; j < 8; j++) {
                    unsigned bb[2];
                    if (kk == 0) { bb[0] = B[j].x; bb[1] = B[j].y; }
                    else         { bb[0] = B[j].z; bb[1] = B[j].w; }
                    mma_tf32(acc[i][j], a, bb);
                }
            }
        }
    };

    // ================= layer 1: K = 512, 32 chunks =================
    loadX1(0, 0);
    loadW(w1p, 0); CP_COMMIT();
    CP_WAIT0();
    __syncthreads();
    for (int c = 0; c < 32; c++) {
        if (c + 1 < 32) {
            int nb = (c + 1) & 1;
            loadX1(c + 1, nb);
            loadW(w1p + (size_t)(c + 1) * 4096, nb); CP_COMMIT();
        }
        compute((const unsigned*)(sX + (c & 1) * XBUF),
                (const unsigned*)(sW + (c & 1) * WBUF));
        if (c + 1 < 32) CP_WAIT0();
        __syncthreads();
    }

    // prefetch layer-2 W chunk 0 while doing epilogue 1
    loadW(w2p, 0); CP_COMMIT();

    // epilogue 1: bias + tanh -> packed sH chunks, reset acc
    {
        unsigned* sHu = (unsigned*)sH;
        const int t = wr * 4; // + i below
#pragma unroll
        for (int i = 0; i < 4; i++) {
#pragma unroll
            for (int j = 0; j < 8; j++) {
                int col0 = wc * 64 + j * 8 + 2 * t4;
                float v00 = fast_tanh(acc[i][j][0] + b1s[col0]);
                float v01 = fast_tanh(acc[i][j][1] + b1s[col0 + 1]);
                float v10 = fast_tanh(acc[i][j][2] + b1s[col0]);
                float v11 = fast_tanh(acc[i][j][3] + b1s[col0 + 1]);
                unsigned vals[4] = {f2tf(v00), f2tf(v01), f2tf(v10), f2tf(v11)};
#pragma unroll
                for (int e = 0; e < 4; e++) {
                    int col = col0 + (e & 1);
                    int half = e >> 1;
                    int ch = col >> 4, klocal = col & 15;
                    int kk = klocal >> 3, t4k = klocal & 3, q2 = (klocal >> 2) & 1;
                    unsigned u16 = (t + i) * 64 + (g * 4 + t4k) * 2 + kk;
                    unsigned us = u16 ^ ((u16 >> 3) & 7);
                    sHu[ch * 2048 + us * 4 + q2 * 2 + half] = vals[e];
                }
                acc[i][j][0] = acc[i][j][1] = acc[i][j][2] = acc[i][j][3] = 0.0f;
            }
        }
    }
    CP_WAIT0();
    __syncthreads();

    // ================= layer 2: K = 256, 16 chunks (A = packed sH) =========
    for (int c = 0; c < 16; c++) {
        if (c + 1 < 16) {
            loadW(w2p + (size_t)(c + 1) * 4096, (c + 1) & 1); CP_COMMIT();
        }
        compute((const unsigned*)(sH + c * 2048),
                (const unsigned*)(sW + (c & 1) * WBUF));
        if (c + 1 < 16) CP_WAIT0();
        __syncthreads();
    }

    // epilogue 2: tanh + dot W3 + reduce -> g_mlp
    {
#pragma unroll
        for (int i = 0; i < 4; i++) {
            float v0 = 0.0f, v1 = 0.0f;
#pragma unroll
            for (int j = 0; j < 8; j++) {
                int col = wc * 64 + j * 8 + t4 * 2;
                v0 += fast_tanh(acc[i][j][0] + b2s[col]) * w3s[col]
                    + fast_tanh(acc[i][j][1] + b2s[col + 1]) * w3s[col + 1];
                v1 += fast_tanh(acc[i][j][2] + b2s[col]) * w3s[col]
                    + fast_tanh(acc[i][j][3] + b2s[col + 1]) * w3s[col + 1];
            }
            v0 += __shfl_xor_sync(0xffffffffu, v0, 1);
            v0 += __shfl_xor_sync(0xffffffffu, v0, 2);
            v1 += __shfl_xor_sync(0xffffffffu, v1, 1);
            v1 += __shfl_xor_sync(0xffffffffu, v1, 2);
            if (t4 == 0) {
                int row0 = wr * 64 + i * 16 + g;
                sRed[wc * 128 + row0]     = v0;
                sRed[wc * 128 + row0 + 8] = v1;
            }
        }
    }
    __syncthreads();
    if (tid < 128) {
        int gg = m0 + tid;
        if (gg < A)
            g_mlp[p][gg] = sRed[tid] + sRed[128 + tid] + sRed[256 + tid] + sRed[384 + tid] + b3[p];
    }
}

// ---------------------------------------------------------------------------
// E(theta, outs) + deterministic per-segment reduction
// ---------------------------------------------------------------------------
__global__ void seg_kernel(const int* __restrict__ num_angles, float* __restrict__ out, int A) {
    const float TH0 = 1.3824383f, KH = 3.1622777f;
    int b = blockIdx.x;
    int start = 0;
    for (int i = 0; i < b; i++) start += num_angles[i];
    int cnt = num_angles[b];
    if (start + cnt > A) cnt = A - start;

    float accv = 0.0f;
    for (int i = threadIdx.x; i < cnt; i += blockDim.x) {
        int g = start + i;
        float th = g_theta[g];
        float o0 = g_mlp[0][g], o1 = g_mlp[1][g], o2 = g_mlp[2][g];
        float o3 = g_mlp[3][g], o4 = g_mlp[4][g], o5 = g_mlp[5][g];
        float t0h = TH0 + o0; t0h *= t0h;
        float kh = KH + o1; kh *= kh;
        float d = th - t0h;
        float E = 0.5f * kh * d * d;
        float t0c = o2 * o2, kc = o3 * o3;
        float dc = th - t0c;
        E += 0.5f * kc * dc * dc * dc;
        float t0q = o4 * o4, kq = o5 * o5;
        float dq = th - t0q, dq2 = dq * dq;
        E += 0.5f * kq * dq2 * dq2;
        accv += E;
    }
    __shared__ float red[256];
    red[threadIdx.x] = accv;
    __syncthreads();
    for (int s = 128; s > 0; s >>= 1) {
        if (threadIdx.x < s) red[threadIdx.x] += red[threadIdx.x + s];
        __syncthreads();
    }
    if (threadIdx.x == 0) out[b] = red[0];
}

// ---------------------------------------------------------------------------
extern "C" void kernel_launch(void* const* d_in, const int* in_sizes, int n_in,
                              void* d_out, int out_size) {
    const float* r          = (const float*)d_in[0];
    const float* xyz        = (const float*)d_in[1];
    const int*   angles     = (const int*)d_in[2];
    const int*   num_angles = (const int*)d_in[3];
    const float* W1 = (const float*)d_in[4];
    const float* b1 = (const float*)d_in[5];
    const float* W2 = (const float*)d_in[6];
    const float* b2 = (const float*)d_in[7];
    const float* W3 = (const float*)d_in[8];
    const float* b3 = (const float*)d_in[9];
    int A = in_sizes[2] / 3;
    int B = in_sizes[3];

    cudaFuncSetAttribute(mlp_mma_kernel, cudaFuncAttributeMaxDynamicSharedMemorySize, SMEM_TOT);

    prep_w1<<<768, 256>>>(W1);
    prep_w2<<<384, 256>>>(W2);
    geom_kernel<<<(A + 255) / 256, 256>>>(xyz, angles, A);
    dim3 grid((A + 127) / 128, PNUM);
    mlp_mma_kernel<<<grid, 256, SMEM_TOT>>>(r, angles, b1, b2, W3, b3, A);
    seg_kernel<<<B, 256>>>(num_angles, (float*)d_out, A);
}

// round 10
// speedup vs baseline: 2.8385x; 1.0890x over previous
#include <cuda_runtime.h>

#define FR   256
#define DIN  512
#define HH   256
#define PNUM 6
#define MAXA 204800

// ---------------- static device scratch ----------------
__device__ float g_theta[MAXA];
__device__ float g_mlp[PNUM][MAXA];
// fragment-packed tf32 weights: per head, per 16-k chunk, 1024 x 16B units
__device__ unsigned int g_W1P[PNUM * 32 * 4096];
__device__ unsigned int g_W2P[PNUM * 16 * 4096];

__device__ __forceinline__ unsigned f2tf(float x) {
    unsigned u; asm("cvt.rna.tf32.f32 %0, %1;" : "=r"(u) : "f"(x)); return u;
}
__device__ __forceinline__ float fast_tanh(float x) {
    float e = __expf(2.0f * x);
    return 1.0f - __fdividef(2.0f, e + 1.0f);
}
__device__ __forceinline__ void mma_tf32(float* c, const unsigned* a, const unsigned* b) {
    asm volatile(
        "mma.sync.aligned.m16n8k8.row.col.f32.tf32.tf32.f32 "
        "{%0,%1,%2,%3}, {%4,%5,%6,%7}, {%8,%9}, {%0,%1,%2,%3};"
        : "+f"(c[0]), "+f"(c[1]), "+f"(c[2]), "+f"(c[3])
        : "r"(a[0]), "r"(a[1]), "r"(a[2]), "r"(a[3]), "r"(b[0]), "r"(b[1]));
}
__device__ __forceinline__ unsigned smem_u32(const void* p) {
    unsigned a;
    asm("{ .reg .u64 t; cvta.to.shared.u64 t, %1; cvt.u32.u64 %0, t; }" : "=r"(a) : "l"(p));
    return a;
}
#define CP_ASYNC16(dst, src) asm volatile("cp.async.cg.shared.global [%0], [%1], 16;" :: "r"(dst), "l"(src) : "memory")
#define CP_COMMIT() asm volatile("cp.async.commit_group;" ::: "memory")
#define CP_WAIT2()  asm volatile("cp.async.wait_group 2;" ::: "memory")

// ---------------- smem layout (floats) ----------------
#define XBUF  2048            // one packed 128x16 A chunk
#define WBUF  4096            // one packed 256x16 B chunk (ring stage)
#define OFF_SX   0                         // 2 stages
#define OFF_SW   (OFF_SX + 2 * XBUF)       // 4-stage W ring
#define OFF_SH   (OFF_SW + 4 * WBUF)       // 16 packed A chunks (layer-2 A)
#define OFF_B1S  (OFF_SH + 32768)
#define OFF_B2S  (OFF_B1S + 256)
#define OFF_W3S  (OFF_B2S + 256)
#define OFF_RED  (OFF_W3S + 256)
#define OFF_IDX  (OFF_RED + 512)
#define SMEM_FLOATS (OFF_IDX + 384)
#define SMEM_TOT (SMEM_FLOATS * 4)

// ---------------------------------------------------------------------------
// prep: W[p][k][n] -> fragment-packed tf32 units
// ---------------------------------------------------------------------------
__global__ void prep_w1(const float* __restrict__ W1) {
    int u = blockIdx.x * 256 + threadIdx.x;   // 196608 units
    int p = u >> 15, rem = u & 32767;
    int c = rem >> 10, ub = rem & 1023;
    int lane = ub & 31, g = lane >> 2, t4 = lane & 3;
    int j = (ub >> 5) & 7, wcq = ub >> 8;
    int n = wcq * 64 + j * 8 + g;
    const float* src = W1 + ((size_t)p * DIN + c * 16 + t4) * HH + n;
    uint4 o;
    o.x = f2tf(src[0]); o.y = f2tf(src[4 * HH]);
    o.z = f2tf(src[8 * HH]); o.w = f2tf(src[12 * HH]);
    *(uint4*)(g_W1P + (size_t)u * 4) = o;
}
__global__ void prep_w2(const float* __restrict__ W2) {
    int u = blockIdx.x * 256 + threadIdx.x;   // 98304 units
    int p = u >> 14, rem = u & 16383;
    int c = rem >> 10, ub = rem & 1023;
    int lane = ub & 31, g = lane >> 2, t4 = lane & 3;
    int j = (ub >> 5) & 7, wcq = ub >> 8;
    int n = wcq * 64 + j * 8 + g;
    const float* src = W2 + ((size_t)p * HH + c * 16 + t4) * HH + n;
    uint4 o;
    o.x = f2tf(src[0]); o.y = f2tf(src[4 * HH]);
    o.z = f2tf(src[8 * HH]); o.w = f2tf(src[12 * HH]);
    *(uint4*)(g_W2P + (size_t)u * 4) = o;
}

// ---------------------------------------------------------------------------
// geometry -> theta
// ---------------------------------------------------------------------------
__global__ void geom_kernel(const float* __restrict__ xyz,
                            const int* __restrict__ angles, int A) {
    int i = blockIdx.x * blockDim.x + threadIdx.x;
    if (i >= A) return;
    int a0 = angles[3 * i], a1 = angles[3 * i + 1], a2 = angles[3 * i + 2];
    float x0 = xyz[3 * a0], y0 = xyz[3 * a0 + 1], z0 = xyz[3 * a0 + 2];
    float x1 = xyz[3 * a1], y1 = xyz[3 * a1 + 1], z1 = xyz[3 * a1 + 2];
    float x2 = xyz[3 * a2], y2 = xyz[3 * a2 + 1], z2 = xyz[3 * a2 + 2];
    float v1x = x1 - x0, v1y = y1 - y0, v1z = z1 - z0;
    float v2x = x2 - x1, v2y = y2 - y1, v2z = z2 - z1;
    float dot = -(v1x * v2x + v1y * v2y + v1z * v2z);
    float nrm = sqrtf((v1x * v1x + v1y * v1y + v1z * v1z) *
                      (v2x * v2x + v2y * v2y + v2z * v2z));
    g_theta[i] = acosf((dot / nrm) / 1.000001f);
}

// ---------------------------------------------------------------------------
// fused MLP, mma.sync tf32, software-pipelined (deferred STS + 4-stage W ring)
// ---------------------------------------------------------------------------
__global__ void __launch_bounds__(256, 1)
mlp_mma_kernel(const float* __restrict__ r, const int* __restrict__ angles,
               const float* __restrict__ b1, const float* __restrict__ b2,
               const float* __restrict__ W3, const float* __restrict__ b3, int A) {
    extern __shared__ float smem[];
    float* sX  = smem + OFF_SX;
    float* sW  = smem + OFF_SW;
    float* sH  = smem + OFF_SH;
    float* b1s = smem + OFF_B1S;
    float* b2s = smem + OFF_B2S;
    float* w3s = smem + OFF_W3S;
    float* sRed = smem + OFF_RED;
    int*   sIdx = (int*)(smem + OFF_IDX);

    const int tid = threadIdx.x, lane = tid & 31;
    const int w = tid >> 5, wr = w & 1, wc = w >> 1;
    const int g = lane >> 2, t4 = lane & 3;
    const int p = blockIdx.y, m0 = blockIdx.x * 128;
    const unsigned swBase = smem_u32(sW);

    if (tid < 128) {
        int gg = m0 + tid;
        int bi = (gg < A) ? 3 * gg : 0;
        sIdx[tid] = angles[bi]; sIdx[128 + tid] = angles[bi + 1]; sIdx[256 + tid] = angles[bi + 2];
    }
    b1s[tid] = b1[p * HH + tid];
    b2s[tid] = b2[p * HH + tid];
    w3s[tid] = W3[p * HH + tid];
    __syncthreads();

    const unsigned* w1p = g_W1P + (size_t)p * 32 * 4096;
    const unsigned* w2p = g_W2P + (size_t)p * 16 * 4096;

    // X gather: LDG phase (to regs) and STS phase (packed scatter), separated
    auto ldgX = [&](int c, float4* v) {
#pragma unroll
        for (int q = 0; q < 2; q++) {
            int idx = tid + 256 * q;
            int row = idx >> 2, kl = (idx & 3) * 4, kg = c * 16 + kl;
            if (kg < FR) {
                float4 u = *(const float4*)(r + (size_t)sIdx[row] * FR + kg);
                float4 x = *(const float4*)(r + (size_t)sIdx[256 + row] * FR + kg);
                v[q] = make_float4(u.x + x.x, u.y + x.y, u.z + x.z, u.w + x.w);
            } else {
                v[q] = *(const float4*)(r + (size_t)sIdx[128 + row] * FR + kg - FR);
            }
        }
    };
    auto stsX = [&](int b, const float4* v) {
        unsigned* dst = (unsigned*)(sX + b * XBUF);
#pragma unroll
        for (int q = 0; q < 2; q++) {
            int idx = tid + 256 * q;
            int row = idx >> 2, kl = (idx & 3) * 4;
            unsigned f[4] = {f2tf(v[q].x), f2tf(v[q].y), f2tf(v[q].z), f2tf(v[q].w)};
            int t = row >> 4, gr = row & 7, half = (row >> 3) & 1;
            int kk = kl >> 3, q2 = (kl >> 2) & 1;
#pragma unroll
            for (int e = 0; e < 4; e++) {
                unsigned u16 = t * 64 + (gr * 4 + e) * 2 + kk;
                unsigned us = u16 ^ ((u16 >> 3) & 7);
                dst[us * 4 + q2 * 2 + half] = f[e];
            }
        }
    };
    // one packed W chunk (16 KB) -> ring stage b
    auto loadW = [&](const unsigned* srcChunk, int b) {
        unsigned dst = swBase + (unsigned)(b * WBUF * 4);
#pragma unroll
        for (int q = 0; q < 4; q++) {
            int idx = tid + 256 * q;
            CP_ASYNC16(dst + idx * 16, srcChunk + (size_t)idx * 4);
        }
    };

    float acc[4][8][4];
#pragma unroll
    for (int i = 0; i < 4; i++)
#pragma unroll
        for (int j = 0; j < 8; j++)
#pragma unroll
            for (int q = 0; q < 4; q++) acc[i][j][q] = 0.0f;

    auto compute = [&](const unsigned* Xb, const unsigned* Wb) {
        uint4 B[8];
#pragma unroll
        for (int j = 0; j < 8; j++)
            B[j] = *(const uint4*)(Wb + ((wc * 8 + j) * 32 + lane) * 4);
#pragma unroll
        for (int i = 0; i < 4; i++) {
            int t = wr * 4 + i;
#pragma unroll
            for (int kk = 0; kk < 2; kk++) {
                unsigned u16 = t * 64 + lane * 2 + kk;
                unsigned us = u16 ^ ((u16 >> 3) & 7);
                uint4 Aa = *(const uint4*)(Xb + us * 4);
                unsigned a[4] = {Aa.x, Aa.y, Aa.z, Aa.w};
#pragma unroll
                for (int j = 0; j < 8; j++) {
                    unsigned bb[2];
                    if (kk == 0) { bb[0] = B[j].x; bb[1] = B[j].y; }
                    else         { bb[0] = B[j].z; bb[1] = B[j].w; }
                    mma_tf32(acc[i][j], a, bb);
                }
            }
        }
    };

    // ================= layer 1: K = 512, 32 chunks, pipelined =================
    float4 xv[2];
    ldgX(0, xv); stsX(0, xv);
    loadW(w1p, 0);                       CP_COMMIT();   // group 0
    loadW(w1p + 4096, 1);                CP_COMMIT();   // group 1
    loadW(w1p + 2 * 4096, 2);            CP_COMMIT();   // group 2
    ldgX(1, xv);
    CP_WAIT2();                                          // W(0) done
    __syncthreads();
    for (int c = 0; c < 32; c++) {
        int nc = (c + 3 < 32) ? c + 3 : 31;              // clamped re-issue keeps group math constant
        loadW(w1p + (size_t)nc * 4096, (c + 3) & 3); CP_COMMIT();
        if (c + 1 < 32) stsX((c + 1) & 1, xv);
        if (c + 2 < 32) ldgX(c + 2, xv);                 // latency hidden by compute below
        compute((const unsigned*)(sX + (c & 1) * XBUF),
                (const unsigned*)(sW + (c & 3) * WBUF));
        CP_WAIT2();                                      // W(c+1) done
        __syncthreads();
    }

    // prefetch layer-2 W chunks 0..2 during epilogue 1
    loadW(w2p, 0);            CP_COMMIT();
    loadW(w2p + 4096, 1);     CP_COMMIT();
    loadW(w2p + 2 * 4096, 2); CP_COMMIT();

    // epilogue 1: bias + tanh -> packed sH chunks, reset acc
    {
        unsigned* sHu = (unsigned*)sH;
        const int t = wr * 4;
#pragma unroll
        for (int i = 0; i < 4; i++) {
#pragma unroll
            for (int j = 0; j < 8; j++) {
                int col0 = wc * 64 + j * 8 + 2 * t4;
                float v00 = fast_tanh(acc[i][j][0] + b1s[col0]);
                float v01 = fast_tanh(acc[i][j][1] + b1s[col0 + 1]);
                float v10 = fast_tanh(acc[i][j][2] + b1s[col0]);
                float v11 = fast_tanh(acc[i][j][3] + b1s[col0 + 1]);
                unsigned vals[4] = {f2tf(v00), f2tf(v01), f2tf(v10), f2tf(v11)};
#pragma unroll
                for (int e = 0; e < 4; e++) {
                    int col = col0 + (e & 1);
                    int half = e >> 1;
                    int ch = col >> 4, klocal = col & 15;
                    int kk = klocal >> 3, t4k = klocal & 3, q2 = (klocal >> 2) & 1;
                    unsigned u16 = (t + i) * 64 + (g * 4 + t4k) * 2 + kk;
                    unsigned us = u16 ^ ((u16 >> 3) & 7);
                    sHu[ch * 2048 + us * 4 + q2 * 2 + half] = vals[e];
                }
                acc[i][j][0] = acc[i][j][1] = acc[i][j][2] = acc[i][j][3] = 0.0f;
            }
        }
    }
    CP_WAIT2();                                          // W2(0) done
    __syncthreads();                                     // also publishes sH

    // ================= layer 2: K = 256, 16 chunks (A = packed sH) =========
    for (int c = 0; c < 16; c++) {
        int nc = (c + 3 < 16) ? c + 3 : 15;
        loadW(w2p + (size_t)nc * 4096, (c + 3) & 3); CP_COMMIT();
        compute((const unsigned*)(sH + c * 2048),
                (const unsigned*)(sW + (c & 3) * WBUF));
        CP_WAIT2();                                      // W2(c+1) done
        __syncthreads();
    }

    // epilogue 2: tanh + dot W3 + reduce -> g_mlp
    {
#pragma unroll
        for (int i = 0; i < 4; i++) {
            float v0 = 0.0f, v1 = 0.0f;
#pragma unroll
            for (int j = 0; j < 8; j++) {
                int col = wc * 64 + j * 8 + t4 * 2;
                v0 += fast_tanh(acc[i][j][0] + b2s[col]) * w3s[col]
                    + fast_tanh(acc[i][j][1] + b2s[col + 1]) * w3s[col + 1];
                v1 += fast_tanh(acc[i][j][2] + b2s[col]) * w3s[col]
                    + fast_tanh(acc[i][j][3] + b2s[col + 1]) * w3s[col + 1];
            }
            v0 += __shfl_xor_sync(0xffffffffu, v0, 1);
            v0 += __shfl_xor_sync(0xffffffffu, v0, 2);
            v1 += __shfl_xor_sync(0xffffffffu, v1, 1);
            v1 += __shfl_xor_sync(0xffffffffu, v1, 2);
            if (t4 == 0) {
                int row0 = wr * 64 + i * 16 + g;
                sRed[wc * 128 + row0]     = v0;
                sRed[wc * 128 + row0 + 8] = v1;
            }
        }
    }
    __syncthreads();
    if (tid < 128) {
        int gg = m0 + tid;
        if (gg < A)
            g_mlp[p][gg] = sRed[tid] + sRed[128 + tid] + sRed[256 + tid] + sRed[384 + tid] + b3[p];
    }
}

// ---------------------------------------------------------------------------
// E(theta, outs) + deterministic per-segment reduction
// ---------------------------------------------------------------------------
__global__ void seg_kernel(const int* __restrict__ num_angles, float* __restrict__ out, int A) {
    const float TH0 = 1.3824383f, KH = 3.1622777f;
    int b = blockIdx.x;
    int start = 0;
    for (int i = 0; i < b; i++) start += num_angles[i];
    int cnt = num_angles[b];
    if (start + cnt > A) cnt = A - start;

    float accv = 0.0f;
    for (int i = threadIdx.x; i < cnt; i += blockDim.x) {
        int g = start + i;
        float th = g_theta[g];
        float o0 = g_mlp[0][g], o1 = g_mlp[1][g], o2 = g_mlp[2][g];
        float o3 = g_mlp[3][g], o4 = g_mlp[4][g], o5 = g_mlp[5][g];
        float t0h = TH0 + o0; t0h *= t0h;
        float kh = KH + o1; kh *= kh;
        float d = th - t0h;
        float E = 0.5f * kh * d * d;
        float t0c = o2 * o2, kc = o3 * o3;
        float dc = th - t0c;
        E += 0.5f * kc * dc * dc * dc;
        float t0q = o4 * o4, kq = o5 * o5;
        float dq = th - t0q, dq2 = dq * dq;
        E += 0.5f * kq * dq2 * dq2;
        accv += E;
    }
    __shared__ float red[256];
    red[threadIdx.x] = accv;
    __syncthreads();
    for (int s = 128; s > 0; s >>= 1) {
        if (threadIdx.x < s) red[threadIdx.x] += red[threadIdx.x + s];
        __syncthreads();
    }
    if (threadIdx.x == 0) out[b] = red[0];
}

// ---------------------------------------------------------------------------
extern "C" void kernel_launch(void* const* d_in, const int* in_sizes, int n_in,
                              void* d_out, int out_size) {
    const float* r          = (const float*)d_in[0];
    const float* xyz        = (const float*)d_in[1];
    const int*   angles     = (const int*)d_in[2];
    const int*   num_angles = (const int*)d_in[3];
    const float* W1 = (const float*)d_in[4];
    const float* b1 = (const float*)d_in[5];
    const float* W2 = (const float*)d_in[6];
    const float* b2 = (const float*)d_in[7];
    const float* W3 = (const float*)d_in[8];
    const float* b3 = (const float*)d_in[9];
    int A = in_sizes[2] / 3;
    int B = in_sizes[3];

    cudaFuncSetAttribute(mlp_mma_kernel, cudaFuncAttributeMaxDynamicSharedMemorySize, SMEM_TOT);

    prep_w1<<<768, 256>>>(W1);
    prep_w2<<<384, 256>>>(W2);
    geom_kernel<<<(A + 255) / 256, 256>>>(xyz, angles, A);
    dim3 grid((A + 127) / 128, PNUM);
    mlp_mma_kernel<<<grid, 256, SMEM_TOT>>>(r, angles, b1, b2, W3, b3, A);
    seg_kernel<<<B, 256>>>(num_angles, (float*)d_out, A);
}

// round 16
// speedup vs baseline: 2.9630x; 1.0439x over previous
#include <cuda_runtime.h>

#define FR   256
#define DIN  512
#define HH   256
#define PNUM 6
#define MAXA 204800
#define NTHR 512

// ---------------- static device scratch ----------------
__device__ float g_theta[MAXA];
__device__ float g_mlp[PNUM][MAXA];
// fragment-packed tf32 weights: per head, per 16-k chunk, 1024 x 16B units
__device__ unsigned int g_W1P[PNUM * 32 * 4096];
__device__ unsigned int g_W2P[PNUM * 16 * 4096];

__device__ __forceinline__ unsigned f2tf(float x) {
    unsigned u; asm("cvt.rna.tf32.f32 %0, %1;" : "=r"(u) : "f"(x)); return u;
}
__device__ __forceinline__ float fast_tanh(float x) {
    float e = __expf(2.0f * x);
    return 1.0f - __fdividef(2.0f, e + 1.0f);
}
__device__ __forceinline__ void mma_tf32(float* c, const unsigned* a, const unsigned* b) {
    asm volatile(
        "mma.sync.aligned.m16n8k8.row.col.f32.tf32.tf32.f32 "
        "{%0,%1,%2,%3}, {%4,%5,%6,%7}, {%8,%9}, {%0,%1,%2,%3};"
        : "+f"(c[0]), "+f"(c[1]), "+f"(c[2]), "+f"(c[3])
        : "r"(a[0]), "r"(a[1]), "r"(a[2]), "r"(a[3]), "r"(b[0]), "r"(b[1]));
}
__device__ __forceinline__ unsigned smem_u32(const void* p) {
    unsigned a;
    asm("{ .reg .u64 t; cvta.to.shared.u64 t, %1; cvt.u32.u64 %0, t; }" : "=r"(a) : "l"(p));
    return a;
}
#define CP_ASYNC16(dst, src) asm volatile("cp.async.cg.shared.global [%0], [%1], 16;" :: "r"(dst), "l"(src) : "memory")
#define CP_COMMIT() asm volatile("cp.async.commit_group;" ::: "memory")
#define CP_WAIT2()  asm volatile("cp.async.wait_group 2;" ::: "memory")

// ---------------- smem layout (floats) ----------------
#define XBUF  2048            // one packed 128x16 A chunk
#define WBUF  4096            // one packed 256x16 B chunk (ring stage)
#define OFF_SX   0                         // 2 stages
#define OFF_SW   (OFF_SX + 2 * XBUF)       // 4-stage W ring
#define OFF_SH   (OFF_SW + 4 * WBUF)       // 16 packed A chunks (layer-2 A)
#define OFF_B1S  (OFF_SH + 32768)
#define OFF_B2S  (OFF_B1S + 256)
#define OFF_W3S  (OFF_B2S + 256)
#define OFF_RED  (OFF_W3S + 256)
#define OFF_IDX  (OFF_RED + 512)
#define SMEM_FLOATS (OFF_IDX + 384)
#define SMEM_TOT (SMEM_FLOATS * 4)

// ---------------------------------------------------------------------------
// prep: W[p][k][n] -> fragment-packed tf32 units
// ---------------------------------------------------------------------------
__global__ void prep_w1(const float* __restrict__ W1) {
    int u = blockIdx.x * 256 + threadIdx.x;   // 196608 units
    int p = u >> 15, rem = u & 32767;
    int c = rem >> 10, ub = rem & 1023;
    int lane = ub & 31, g = lane >> 2, t4 = lane & 3;
    int j = (ub >> 5) & 7, wcq = ub >> 8;
    int n = wcq * 64 + j * 8 + g;
    const float* src = W1 + ((size_t)p * DIN + c * 16 + t4) * HH + n;
    uint4 o;
    o.x = f2tf(src[0]); o.y = f2tf(src[4 * HH]);
    o.z = f2tf(src[8 * HH]); o.w = f2tf(src[12 * HH]);
    *(uint4*)(g_W1P + (size_t)u * 4) = o;
}
__global__ void prep_w2(const float* __restrict__ W2) {
    int u = blockIdx.x * 256 + threadIdx.x;   // 98304 units
    int p = u >> 14, rem = u & 16383;
    int c = rem >> 10, ub = rem & 1023;
    int lane = ub & 31, g = lane >> 2, t4 = lane & 3;
    int j = (ub >> 5) & 7, wcq = ub >> 8;
    int n = wcq * 64 + j * 8 + g;
    const float* src = W2 + ((size_t)p * HH + c * 16 + t4) * HH + n;
    uint4 o;
    o.x = f2tf(src[0]); o.y = f2tf(src[4 * HH]);
    o.z = f2tf(src[8 * HH]); o.w = f2tf(src[12 * HH]);
    *(uint4*)(g_W2P + (size_t)u * 4) = o;
}

// ---------------------------------------------------------------------------
// geometry -> theta
// ---------------------------------------------------------------------------
__global__ void geom_kernel(const float* __restrict__ xyz,
                            const int* __restrict__ angles, int A) {
    int i = blockIdx.x * blockDim.x + threadIdx.x;
    if (i >= A) return;
    int a0 = angles[3 * i], a1 = angles[3 * i + 1], a2 = angles[3 * i + 2];
    float x0 = xyz[3 * a0], y0 = xyz[3 * a0 + 1], z0 = xyz[3 * a0 + 2];
    float x1 = xyz[3 * a1], y1 = xyz[3 * a1 + 1], z1 = xyz[3 * a1 + 2];
    float x2 = xyz[3 * a2], y2 = xyz[3 * a2 + 1], z2 = xyz[3 * a2 + 2];
    float v1x = x1 - x0, v1y = y1 - y0, v1z = z1 - z0;
    float v2x = x2 - x1, v2y = y2 - y1, v2z = z2 - z1;
    float dot = -(v1x * v2x + v1y * v2y + v1z * v2z);
    float nrm = sqrtf((v1x * v1x + v1y * v1y + v1z * v1z) *
                      (v2x * v2x + v2y * v2y + v2z * v2z));
    g_theta[i] = acosf((dot / nrm) / 1.000001f);
}

// ---------------------------------------------------------------------------
// fused MLP, mma.sync tf32, 16 warps (4x4 grid), pipelined loaders.
// ---------------------------------------------------------------------------
__global__ void __launch_bounds__(NTHR, 1)
mlp_mma_kernel(const float* __restrict__ r, const int* __restrict__ angles,
               const float* __restrict__ b1, const float* __restrict__ b2,
               const float* __restrict__ W3, const float* __restrict__ b3, int A) {
    extern __shared__ float smem[];
    float* sX  = smem + OFF_SX;
    float* sW  = smem + OFF_SW;
    float* sH  = smem + OFF_SH;
    float* b1s = smem + OFF_B1S;
    float* b2s = smem + OFF_B2S;
    float* w3s = smem + OFF_W3S;
    float* sRed = smem + OFF_RED;
    int*   sIdx = (int*)(smem + OFF_IDX);

    const int tid = threadIdx.x, lane = tid & 31;
    const int w = tid >> 5, wr = w & 3, wc = w >> 2;   // 4 row-groups x 4 col-groups
    const int g = lane >> 2, t4 = lane & 3;
    const int p = blockIdx.y, m0 = blockIdx.x * 128;
    const unsigned swBase = smem_u32(sW);

    if (tid < 128) {
        int gg = m0 + tid;
        int bi = (gg < A) ? 3 * gg : 0;
        sIdx[tid] = angles[bi]; sIdx[128 + tid] = angles[bi + 1]; sIdx[256 + tid] = angles[bi + 2];
    }
    if (tid < 256) {
        b1s[tid] = b1[p * HH + tid];
        b2s[tid] = b2[p * HH + tid];
        w3s[tid] = W3[p * HH + tid];
    }
    __syncthreads();

    const unsigned* w1p = g_W1P + (size_t)p * 32 * 4096;
    const unsigned* w2p = g_W2P + (size_t)p * 16 * 4096;

    // X gather: LDG phase (to regs) and STS phase (packed scatter), separated
    auto ldgX = [&](int c, float4& v) {
        int row = tid >> 2, kl = (tid & 3) * 4, kg = c * 16 + kl;
        if (kg < FR) {
            float4 u = *(const float4*)(r + (size_t)sIdx[row] * FR + kg);
            float4 x = *(const float4*)(r + (size_t)sIdx[256 + row] * FR + kg);
            v = make_float4(u.x + x.x, u.y + x.y, u.z + x.z, u.w + x.w);
        } else {
            v = *(const float4*)(r + (size_t)sIdx[128 + row] * FR + kg - FR);
        }
    };
    auto stsX = [&](int b, const float4& v) {
        unsigned* dst = (unsigned*)(sX + b * XBUF);
        int row = tid >> 2, kl = (tid & 3) * 4;
        unsigned f[4] = {f2tf(v.x), f2tf(v.y), f2tf(v.z), f2tf(v.w)};
        int t = row >> 4, gr = row & 7, half = (row >> 3) & 1;
        int kk = kl >> 3, q2 = (kl >> 2) & 1;
#pragma unroll
        for (int e = 0; e < 4; e++) {
            unsigned u16 = t * 64 + (gr * 4 + e) * 2 + kk;
            unsigned us = u16 ^ ((u16 >> 3) & 7);
            dst[us * 4 + q2 * 2 + half] = f[e];
        }
    };
    // one packed W chunk (16 KB) -> ring stage b
    auto loadW = [&](const unsigned* srcChunk, int b) {
        unsigned dst = swBase + (unsigned)(b * WBUF * 4);
#pragma unroll
        for (int q = 0; q < 2; q++) {
            int idx = tid + NTHR * q;
            CP_ASYNC16(dst + idx * 16, srcChunk + (size_t)idx * 4);
        }
    };

    float acc[2][8][4];
#pragma unroll
    for (int i = 0; i < 2; i++)
#pragma unroll
        for (int j = 0; j < 8; j++)
#pragma unroll
            for (int q = 0; q < 4; q++) acc[i][j][q] = 0.0f;

    // one 16-k chunk: 8 B LDS.128 + 4 A LDS.128 + 32 MMA per warp
    auto compute = [&](const unsigned* Xb, const unsigned* Wb) {
        uint4 B[8];
#pragma unroll
        for (int j = 0; j < 8; j++)
            B[j] = *(const uint4*)(Wb + ((wc * 8 + j) * 32 + lane) * 4);
#pragma unroll
        for (int i = 0; i < 2; i++) {
            int t = wr * 2 + i;
#pragma unroll
            for (int kk = 0; kk < 2; kk++) {
                unsigned u16 = t * 64 + lane * 2 + kk;
                unsigned us = u16 ^ ((u16 >> 3) & 7);
                uint4 Aa = *(const uint4*)(Xb + us * 4);
                unsigned a[4] = {Aa.x, Aa.y, Aa.z, Aa.w};
#pragma unroll
                for (int j = 0; j < 8; j++) {
                    unsigned bb[2];
                    if (kk == 0) { bb[0] = B[j].x; bb[1] = B[j].y; }
                    else         { bb[0] = B[j].z; bb[1] = B[j].w; }
                    mma_tf32(acc[i][j], a, bb);
                }
            }
        }
    };

    // ================= layer 1: K = 512, 32 chunks, pipelined =================
    float4 xv;
    ldgX(0, xv); stsX(0, xv);
    loadW(w1p, 0);                       CP_COMMIT();   // group 0
    loadW(w1p + 4096, 1);                CP_COMMIT();   // group 1
    loadW(w1p + 2 * 4096, 2);            CP_COMMIT();   // group 2
    ldgX(1, xv);
    CP_WAIT2();                                          // W(0) done
    __syncthreads();
    for (int c = 0; c < 32; c++) {
        int nc = (c + 3 < 32) ? c + 3 : 31;              // clamped re-issue keeps group math constant
        loadW(w1p + (size_t)nc * 4096, (c + 3) & 3); CP_COMMIT();
        if (c + 1 < 32) stsX((c + 1) & 1, xv);
        if (c + 2 < 32) ldgX(c + 2, xv);                 // latency hidden by compute below
        compute((const unsigned*)(sX + (c & 1) * XBUF),
                (const unsigned*)(sW + (c & 3) * WBUF));
        CP_WAIT2();                                      // W(c+1) done
        __syncthreads();
    }

    // prefetch layer-2 W chunks 0..2 during epilogue 1
    loadW(w2p, 0);            CP_COMMIT();
    loadW(w2p + 4096, 1);     CP_COMMIT();
    loadW(w2p + 2 * 4096, 2); CP_COMMIT();

    // epilogue 1: bias + tanh -> packed sH chunks, reset acc
    {
        unsigned* sHu = (unsigned*)sH;
        const int t = wr * 2;
#pragma unroll
        for (int i = 0; i < 2; i++) {
#pragma unroll
            for (int j = 0; j < 8; j++) {
                int col0 = wc * 64 + j * 8 + 2 * t4;
                float v00 = fast_tanh(acc[i][j][0] + b1s[col0]);
                float v01 = fast_tanh(acc[i][j][1] + b1s[col0 + 1]);
                float v10 = fast_tanh(acc[i][j][2] + b1s[col0]);
                float v11 = fast_tanh(acc[i][j][3] + b1s[col0 + 1]);
                unsigned vals[4] = {f2tf(v00), f2tf(v01), f2tf(v10), f2tf(v11)};
#pragma unroll
                for (int e = 0; e < 4; e++) {
                    int col = col0 + (e & 1);
                    int half = e >> 1;
                    int ch = col >> 4, klocal = col & 15;
                    int kk = klocal >> 3, t4k = klocal & 3, q2 = (klocal >> 2) & 1;
                    unsigned u16 = (t + i) * 64 + (g * 4 + t4k) * 2 + kk;
                    unsigned us = u16 ^ ((u16 >> 3) & 7);
                    sHu[ch * 2048 + us * 4 + q2 * 2 + half] = vals[e];
                }
                acc[i][j][0] = acc[i][j][1] = acc[i][j][2] = acc[i][j][3] = 0.0f;
            }
        }
    }
    CP_WAIT2();                                          // W2(0) done
    __syncthreads();                                     // also publishes sH

    // ================= layer 2: K = 256, 16 chunks (A = packed sH) =========
    for (int c = 0; c < 16; c++) {
        int nc = (c + 3 < 16) ? c + 3 : 15;
        loadW(w2p + (size_t)nc * 4096, (c + 3) & 3); CP_COMMIT();
        compute((const unsigned*)(sH + c * 2048),
                (const unsigned*)(sW + (c & 3) * WBUF));
        CP_WAIT2();                                      // W2(c+1) done
        __syncthreads();
    }

    // epilogue 2: tanh + dot W3 + reduce -> g_mlp
    {
#pragma unroll
        for (int i = 0; i < 2; i++) {
            float v0 = 0.0f, v1 = 0.0f;
#pragma unroll
            for (int j = 0; j < 8; j++) {
                int col = wc * 64 + j * 8 + t4 * 2;
                v0 += fast_tanh(acc[i][j][0] + b2s[col]) * w3s[col]
                    + fast_tanh(acc[i][j][1] + b2s[col + 1]) * w3s[col + 1];
                v1 += fast_tanh(acc[i][j][2] + b2s[col]) * w3s[col]
                    + fast_tanh(acc[i][j][3] + b2s[col + 1]) * w3s[col + 1];
            }
            v0 += __shfl_xor_sync(0xffffffffu, v0, 1);
            v0 += __shfl_xor_sync(0xffffffffu, v0, 2);
            v1 += __shfl_xor_sync(0xffffffffu, v1, 1);
            v1 += __shfl_xor_sync(0xffffffffu, v1, 2);
            if (t4 == 0) {
                int row0 = wr * 32 + i * 16 + g;
                sRed[wc * 128 + row0]     = v0;
                sRed[wc * 128 + row0 + 8] = v1;
            }
        }
    }
    __syncthreads();
    if (tid < 128) {
        int gg = m0 + tid;
        if (gg < A)
            g_mlp[p][gg] = sRed[tid] + sRed[128 + tid] + sRed[256 + tid] + sRed[384 + tid] + b3[p];
    }
}

// ---------------------------------------------------------------------------
// E(theta, outs) + deterministic per-segment reduction
// ---------------------------------------------------------------------------
__global__ void seg_kernel(const int* __restrict__ num_angles, float* __restrict__ out, int A) {
    const float TH0 = 1.3824383f, KH = 3.1622777f;
    int b = blockIdx.x;
    int start = 0;
    for (int i = 0; i < b; i++) start += num_angles[i];
    int cnt = num_angles[b];
    if (start + cnt > A) cnt = A - start;

    float accv = 0.0f;
    for (int i = threadIdx.x; i < cnt; i += blockDim.x) {
        int g = start + i;
        float th = g_theta[g];
        float o0 = g_mlp[0][g], o1 = g_mlp[1][g], o2 = g_mlp[2][g];
        float o3 = g_mlp[3][g], o4 = g_mlp[4][g], o5 = g_mlp[5][g];
        float t0h = TH0 + o0; t0h *= t0h;
        float kh = KH + o1; kh *= kh;
        float d = th - t0h;
        float E = 0.5f * kh * d * d;
        float t0c = o2 * o2, kc = o3 * o3;
        float dc = th - t0c;
        E += 0.5f * kc * dc * dc * dc;
        float t0q = o4 * o4, kq = o5 * o5;
        float dq = th - t0q, dq2 = dq * dq;
        E += 0.5f * kq * dq2 * dq2;
        accv += E;
    }
    __shared__ float red[256];
    red[threadIdx.x] = accv;
    __syncthreads();
    for (int s = 128; s > 0; s >>= 1) {
        if (threadIdx.x < s) red[threadIdx.x] += red[threadIdx.x + s];
        __syncthreads();
    }
    if (threadIdx.x == 0) out[b] = red[0];
}

// ---------------------------------------------------------------------------
extern "C" void kernel_launch(void* const* d_in, const int* in_sizes, int n_in,
                              void* d_out, int out_size) {
    const float* r          = (const float*)d_in[0];
    const float* xyz        = (const float*)d_in[1];
    const int*   angles     = (const int*)d_in[2];
    const int*   num_angles = (const int*)d_in[3];
    const float* W1 = (const float*)d_in[4];
    const float* b1 = (const float*)d_in[5];
    const float* W2 = (const float*)d_in[6];
    const float* b2 = (const float*)d_in[7];
    const float* W3 = (const float*)d_in[8];
    const float* b3 = (const float*)d_in[9];
    int A = in_sizes[2] / 3;
    int B = in_sizes[3];

    cudaFuncSetAttribute(mlp_mma_kernel, cudaFuncAttributeMaxDynamicSharedMemorySize, SMEM_TOT);

    prep_w1<<<768, 256>>>(W1);
    prep_w2<<<384, 256>>>(W2);
    geom_kernel<<<(A + 255) / 256, 256>>>(xyz, angles, A);
    dim3 grid((A + 127) / 128, PNUM);
    mlp_mma_kernel<<<grid, NTHR, SMEM_TOT>>>(r, angles, b1, b2, W3, b3, A);
    seg_kernel<<<B, 256>>>(num_angles, (float*)d_out, A);
}